// round 6
// baseline (speedup 1.0000x reference)
#include <cuda_runtime.h>
#include <cuda_fp16.h>
#include <cstdint>
#include <math.h>

// Problem constants (FlaxGrok1SparseMoeBlock: B=2,S=1024 -> T=2048, H=1024, I=4096, E=8, K=2)
#define T_TOKENS 2048
#define HDIM 1024
#define IDIM 4096
#define NEXP 8
#define NPAIR (T_TOKENS * 2)

// ---------------- device scratch (static; no runtime allocation) ----------------
__device__ int    d_counts[NEXP];
__device__ int    d_offsets[NEXP];
__device__ int    d_cursor[NEXP];
__device__ int    d_tok[NPAIR];
__device__ float  d_wt[NPAIR];
__device__ int    d_slot[NPAIR];
__device__ int    d_te[NPAIR];
__device__ float  d_tw[NPAIR];
__device__ __half d_act_h[(size_t)NPAIR * IDIM];  // 32 MB (half)
__device__ float  d_yscr[(size_t)NPAIR * HDIM];   // 16 MB

// ---------------- helpers ----------------
__device__ __forceinline__ uint32_t smem_u32(const void* p) {
    uint32_t a;
    asm("{ .reg .u64 t; cvta.to.shared.u64 t, %1; cvt.u32.u64 %0, t; }" : "=r"(a) : "l"(p));
    return a;
}
__device__ __forceinline__ uint32_t packh2(float lo, float hi) {
    __half2 h = __floats2half2_rn(lo, hi);
    return *(uint32_t*)&h;
}
__device__ __forceinline__ void mma_f16(float c[4], const uint32_t a[4], const uint32_t b[2]) {
    asm volatile(
        "mma.sync.aligned.m16n8k16.row.col.f32.f16.f16.f32 "
        "{%0,%1,%2,%3}, {%4,%5,%6,%7}, {%8,%9}, {%0,%1,%2,%3};"
        : "+f"(c[0]), "+f"(c[1]), "+f"(c[2]), "+f"(c[3])
        : "r"(a[0]), "r"(a[1]), "r"(a[2]), "r"(a[3]), "r"(b[0]), "r"(b[1]));
}
__device__ __forceinline__ void ldsm_x4(uint32_t r[4], uint32_t addr) {
    asm volatile("ldmatrix.sync.aligned.m8n8.x4.shared.b16 {%0,%1,%2,%3}, [%4];"
        : "=r"(r[0]), "=r"(r[1]), "=r"(r[2]), "=r"(r[3]) : "r"(addr));
}
__device__ __forceinline__ void ldsm_x4t(uint32_t r[4], uint32_t addr) {
    asm volatile("ldmatrix.sync.aligned.m8n8.x4.trans.shared.b16 {%0,%1,%2,%3}, [%4];"
        : "=r"(r[0]), "=r"(r[1]), "=r"(r[2]), "=r"(r[3]) : "r"(addr));
}
__device__ __forceinline__ float gelu_tanh(float g) {
    float c = g + 0.044715f * g * g * g;
    return 0.5f * g * (1.f + tanhf(0.7978845608028654f * c));
}

// ---------------- kernel 0..3: routing ----------------
__global__ void k_zero() { if (threadIdx.x < NEXP) d_counts[threadIdx.x] = 0; }

__global__ void k_router(const float* __restrict__ x, const float* __restrict__ Wg,
                         float* __restrict__ logits_out) {
    const int t = blockIdx.x;
    const int tid = threadIdx.x;
    const float* xr = x + (size_t)t * HDIM;
    float acc[NEXP];
#pragma unroll
    for (int e = 0; e < NEXP; e++) acc[e] = 0.f;
    for (int h = tid; h < HDIM; h += 256) {
        float xv = xr[h];
#pragma unroll
        for (int e = 0; e < NEXP; e++) acc[e] += xv * Wg[h * NEXP + e];
    }
    __shared__ float red[256];
    __shared__ float lg[NEXP];
#pragma unroll
    for (int e = 0; e < NEXP; e++) {
        red[tid] = acc[e];
        __syncthreads();
        for (int s = 128; s > 0; s >>= 1) { if (tid < s) red[tid] += red[tid + s]; __syncthreads(); }
        if (tid == 0) lg[e] = red[0];
        __syncthreads();
    }
    if (tid == 0) {
        int e0 = 0; float l0 = lg[0];
#pragma unroll
        for (int e = 1; e < NEXP; e++) if (lg[e] > l0) { l0 = lg[e]; e0 = e; }
        int e1 = -1; float l1 = -3.4e38f;
#pragma unroll
        for (int e = 0; e < NEXP; e++) if (e != e0 && lg[e] > l1) { l1 = lg[e]; e1 = e; }
        float tt = expf(l1 - l0);
        float w0 = 1.f / (1.f + tt), w1 = tt / (1.f + tt);
        d_te[2 * t] = e0;     d_tw[2 * t] = w0;
        d_te[2 * t + 1] = e1; d_tw[2 * t + 1] = w1;
        atomicAdd(&d_counts[e0], 1);
        atomicAdd(&d_counts[e1], 1);
        if (logits_out) {
#pragma unroll
            for (int e = 0; e < NEXP; e++) logits_out[(size_t)t * NEXP + e] = lg[e];
        }
    }
}

__global__ void k_scan() {
    int off = 0;
    for (int e = 0; e < NEXP; e++) { d_offsets[e] = off; d_cursor[e] = off; off += d_counts[e]; }
}

__global__ void k_scatter() {
    int i = blockIdx.x * blockDim.x + threadIdx.x;
    if (i >= NPAIR) return;
    int e = d_te[i];
    int pos = atomicAdd(&d_cursor[e], 1);
    d_tok[pos] = i >> 1;
    d_wt[pos]  = d_tw[i];
    d_slot[i]  = pos;
}

// =====================================================================
// GEMM1 (fp16 mma.sync + ldmatrix): g=x@Win[e], v=x@Wv[e], act=gelu(g)*v
//   BM=128, BN=64 (x2 matrices), BK=32; 256 threads; warp tile 32x32
//   3-stage pipeline. smem stage: A 128x80B (stride-5 chunks) = 10240,
//   Bg 32x128B (XOR-swizzled) = 4096, Bv = 4096 -> 18432 B/stage
// =====================================================================
#define NCH1 32
#define G1_STAGE 18432
#define G1_BOFF  10240
#define SM1_BYTES (3 * G1_STAGE)

__global__ __launch_bounds__(256)
void k_gemm1(const float* __restrict__ x, const float* __restrict__ Win,
             const float* __restrict__ Wv) {
    extern __shared__ char smc[];
    const uint32_t smb = smem_u32(smc);
    const int e = blockIdx.z;
    const int cnt = d_counts[e];
    const int m0 = blockIdx.y * 128;
    if (m0 >= cnt) return;
    const int n0 = blockIdx.x * 64;
    const int base = d_offsets[e];
    const int tid = threadIdx.x, lane = tid & 31, wid = tid >> 5;
    const int gid = lane >> 2, t4 = lane & 3;
    const int wm = (wid & 3) * 32, wn = (wid >> 2) * 32;

    // --- writer mappings ---
    const int mA = tid & 127;
    const int kc0 = (tid >> 7) * 2;              // A chunk pair (0 or 2)
    int gmA = m0 + mA;
    const float* xrow = x + (size_t)d_tok[base + (gmA < cnt ? gmA : cnt - 1)] * HDIM + kc0 * 8;
    const int kB = tid >> 3, cB = tid & 7;
    const float* wgp = Win + ((size_t)e * HDIM + kB) * IDIM + n0 + cB * 8;
    const float* wvp = Wv  + ((size_t)e * HDIM + kB) * IDIM + n0 + cB * 8;
    const uint32_t stA0 = (uint32_t)(mA * 5 + kc0) * 16;
    const uint32_t stA1 = stA0 + 16;
    const uint32_t stB  = G1_BOFF + kB * 128 + ((cB ^ (kB & 7)) * 16);

    // --- reader (ldmatrix) lane offsets ---
    const int lrow = (lane & 7) + ((lane >> 3) & 1) * 8;
    const int lsel = lane >> 4;
    uint32_t aoff[2][2], boff[2][2];
#pragma unroll
    for (int mt = 0; mt < 2; mt++)
#pragma unroll
        for (int s = 0; s < 2; s++)
            aoff[mt][s] = (uint32_t)((wm + mt * 16 + lrow) * 5 + 2 * s + lsel) * 16;
#pragma unroll
    for (int s = 0; s < 2; s++)
#pragma unroll
        for (int nh = 0; nh < 2; nh++) {
            int kl = s * 16 + lrow;
            int cl = (wn >> 3) + nh * 2 + lsel;
            boff[s][nh] = G1_BOFF + kl * 128 + ((cl ^ (kl & 7)) * 16);
        }

    float4 pa[4], pg[2], pv[2];
#define LD1(c) do { \
        const float* xr_ = xrow + (c) * 32; \
        pa[0] = *(const float4*)(xr_);      pa[1] = *(const float4*)(xr_ + 4); \
        pa[2] = *(const float4*)(xr_ + 8);  pa[3] = *(const float4*)(xr_ + 12); \
        const float* g_ = wgp + (size_t)(c) * 32 * IDIM; \
        pg[0] = *(const float4*)(g_); pg[1] = *(const float4*)(g_ + 4); \
        const float* v_ = wvp + (size_t)(c) * 32 * IDIM; \
        pv[0] = *(const float4*)(v_); pv[1] = *(const float4*)(v_ + 4); \
    } while (0)
#define ST1(st) do { \
        char* b_ = smc + (st) * G1_STAGE; \
        uint4 u; \
        u.x = packh2(pa[0].x, pa[0].y); u.y = packh2(pa[0].z, pa[0].w); \
        u.z = packh2(pa[1].x, pa[1].y); u.w = packh2(pa[1].z, pa[1].w); \
        *(uint4*)(b_ + stA0) = u; \
        u.x = packh2(pa[2].x, pa[2].y); u.y = packh2(pa[2].z, pa[2].w); \
        u.z = packh2(pa[3].x, pa[3].y); u.w = packh2(pa[3].z, pa[3].w); \
        *(uint4*)(b_ + stA1) = u; \
        u.x = packh2(pg[0].x, pg[0].y); u.y = packh2(pg[0].z, pg[0].w); \
        u.z = packh2(pg[1].x, pg[1].y); u.w = packh2(pg[1].z, pg[1].w); \
        *(uint4*)(b_ + stB) = u; \
        u.x = packh2(pv[0].x, pv[0].y); u.y = packh2(pv[0].z, pv[0].w); \
        u.z = packh2(pv[1].x, pv[1].y); u.w = packh2(pv[1].z, pv[1].w); \
        *(uint4*)(b_ + stB + 4096) = u; \
    } while (0)

    float accg[2][4][4], accv[2][4][4];
#pragma unroll
    for (int i = 0; i < 2; i++)
#pragma unroll
        for (int j = 0; j < 4; j++)
#pragma unroll
            for (int q = 0; q < 4; q++) { accg[i][j][q] = 0.f; accv[i][j][q] = 0.f; }

    LD1(0); ST1(0); LD1(1);
    __syncthreads();

    for (int c = 0; c < NCH1; c++) {
        if (c + 1 < NCH1) ST1((c + 1) % 3);
        if (c + 2 < NCH1) LD1(c + 2);
        __syncthreads();
        const uint32_t sa = smb + (uint32_t)(c % 3) * G1_STAGE;
#pragma unroll
        for (int s = 0; s < 2; s++) {
            uint32_t af[2][4];
            ldsm_x4(af[0], sa + aoff[0][s]);
            ldsm_x4(af[1], sa + aoff[1][s]);
#pragma unroll
            for (int nh = 0; nh < 2; nh++) {
                uint32_t bg[4], bv[4];
                ldsm_x4t(bg, sa + boff[s][nh]);
                ldsm_x4t(bv, sa + boff[s][nh] + 4096);
#pragma unroll
                for (int mt = 0; mt < 2; mt++) {
                    mma_f16(accg[mt][2 * nh],     af[mt], bg);
                    mma_f16(accg[mt][2 * nh + 1], af[mt], bg + 2);
                    mma_f16(accv[mt][2 * nh],     af[mt], bv);
                    mma_f16(accv[mt][2 * nh + 1], af[mt], bv + 2);
                }
            }
        }
    }

    // epilogue: act = gelu(g)*v -> half
#pragma unroll
    for (int mt = 0; mt < 2; mt++) {
#pragma unroll
        for (int nt = 0; nt < 4; nt++) {
            int col = n0 + wn + nt * 8 + t4 * 2;
#pragma unroll
            for (int h = 0; h < 2; h++) {
                int gm = m0 + wm + mt * 16 + gid + h * 8;
                if (gm < cnt) {
                    float a0 = gelu_tanh(accg[mt][nt][h * 2])     * accv[mt][nt][h * 2];
                    float a1 = gelu_tanh(accg[mt][nt][h * 2 + 1]) * accv[mt][nt][h * 2 + 1];
                    *(uint32_t*)(d_act_h + (size_t)(base + gm) * IDIM + col) = packh2(a0, a1);
                }
            }
        }
    }
#undef LD1
#undef ST1
}

// =====================================================================
// GEMM2 (fp16 mma.sync + ldmatrix): y = act@Wout[e] * wt
//   BM=128, BN=128, BK=32; 256 threads; warp tile 32x64
//   smem stage: A 10240 + B 32x256B (XOR-swizzled, 16 chunks) 8192 -> 18432
// =====================================================================
#define NCH2 128
#define G2_STAGE 18432
#define G2_BOFF  10240
#define SM2_BYTES (3 * G2_STAGE)

__global__ __launch_bounds__(256)
void k_gemm2(const float* __restrict__ Wout) {
    extern __shared__ char smc[];
    const uint32_t smb = smem_u32(smc);
    const int e = blockIdx.z;
    const int cnt = d_counts[e];
    const int m0 = blockIdx.y * 128;
    if (m0 >= cnt) return;
    const int n0 = blockIdx.x * 128;
    const int base = d_offsets[e];
    const int tid = threadIdx.x, lane = tid & 31, wid = tid >> 5;
    const int gid = lane >> 2, t4 = lane & 3;
    const int wm = (wid & 3) * 32, wn = (wid >> 2) * 64;

    // --- writer mappings ---
    const int mA = tid & 127;
    const int ca0 = (tid >> 7) * 2;
    int slotA = base + m0 + mA;
    if (slotA > NPAIR - 1) slotA = NPAIR - 1;
    const __half* actrow = d_act_h + (size_t)slotA * IDIM + ca0 * 8;
    const int kB = tid >> 3, cB2 = (tid & 7) * 2;
    const float* wp = Wout + ((size_t)e * IDIM + kB) * HDIM + n0 + cB2 * 8;
    const uint32_t stA0 = (uint32_t)(mA * 5 + ca0) * 16;
    const uint32_t stA1 = stA0 + 16;
    const uint32_t stB0 = G2_BOFF + kB * 256 + (((cB2 & 7) ^ (kB & 7)) | (cB2 & 8)) * 16;
    const uint32_t stB1 = G2_BOFF + kB * 256 + ((((cB2 + 1) & 7) ^ (kB & 7)) | ((cB2 + 1) & 8)) * 16;

    // --- reader lane offsets ---
    const int lrow = (lane & 7) + ((lane >> 3) & 1) * 8;
    const int lsel = lane >> 4;
    uint32_t aoff[2][2], boff[2][4];
#pragma unroll
    for (int mt = 0; mt < 2; mt++)
#pragma unroll
        for (int s = 0; s < 2; s++)
            aoff[mt][s] = (uint32_t)((wm + mt * 16 + lrow) * 5 + 2 * s + lsel) * 16;
#pragma unroll
    for (int s = 0; s < 2; s++)
#pragma unroll
        for (int nh = 0; nh < 4; nh++) {
            int kl = s * 16 + lrow;
            int cl = (wn >> 3) + nh * 2 + lsel;
            boff[s][nh] = G2_BOFF + kl * 256 + ((((cl & 7) ^ (kl & 7)) | (cl & 8)) * 16);
        }

    uint4 qa[2];
    float4 pb[4];
#define LD2(c) do { \
        const __half* ar_ = actrow + (c) * 32; \
        qa[0] = *(const uint4*)(ar_); qa[1] = *(const uint4*)(ar_ + 8); \
        const float* w_ = wp + (size_t)(c) * 32 * HDIM; \
        pb[0] = *(const float4*)(w_);      pb[1] = *(const float4*)(w_ + 4); \
        pb[2] = *(const float4*)(w_ + 8);  pb[3] = *(const float4*)(w_ + 12); \
    } while (0)
#define ST2(st) do { \
        char* b_ = smc + (st) * G2_STAGE; \
        *(uint4*)(b_ + stA0) = qa[0]; \
        *(uint4*)(b_ + stA1) = qa[1]; \
        uint4 u; \
        u.x = packh2(pb[0].x, pb[0].y); u.y = packh2(pb[0].z, pb[0].w); \
        u.z = packh2(pb[1].x, pb[1].y); u.w = packh2(pb[1].z, pb[1].w); \
        *(uint4*)(b_ + stB0) = u; \
        u.x = packh2(pb[2].x, pb[2].y); u.y = packh2(pb[2].z, pb[2].w); \
        u.z = packh2(pb[3].x, pb[3].y); u.w = packh2(pb[3].z, pb[3].w); \
        *(uint4*)(b_ + stB1) = u; \
    } while (0)

    float acc[2][8][4];
#pragma unroll
    for (int i = 0; i < 2; i++)
#pragma unroll
        for (int j = 0; j < 8; j++)
#pragma unroll
            for (int q = 0; q < 4; q++) acc[i][j][q] = 0.f;

    LD2(0); ST2(0); LD2(1);
    __syncthreads();

    for (int c = 0; c < NCH2; c++) {
        if (c + 1 < NCH2) ST2((c + 1) % 3);
        if (c + 2 < NCH2) LD2(c + 2);
        __syncthreads();
        const uint32_t sa = smb + (uint32_t)(c % 3) * G2_STAGE;
#pragma unroll
        for (int s = 0; s < 2; s++) {
            uint32_t af[2][4];
            ldsm_x4(af[0], sa + aoff[0][s]);
            ldsm_x4(af[1], sa + aoff[1][s]);
#pragma unroll
            for (int nh = 0; nh < 4; nh++) {
                uint32_t bf[4];
                ldsm_x4t(bf, sa + boff[s][nh]);
#pragma unroll
                for (int mt = 0; mt < 2; mt++) {
                    mma_f16(acc[mt][2 * nh],     af[mt], bf);
                    mma_f16(acc[mt][2 * nh + 1], af[mt], bf + 2);
                }
            }
        }
    }

#pragma unroll
    for (int mt = 0; mt < 2; mt++) {
#pragma unroll
        for (int nt = 0; nt < 8; nt++) {
            int col = n0 + wn + nt * 8 + t4 * 2;
#pragma unroll
            for (int h = 0; h < 2; h++) {
                int gm = m0 + wm + mt * 16 + gid + h * 8;
                if (gm < cnt) {
                    float wt = d_wt[base + gm];
                    float2 r;
                    r.x = acc[mt][nt][h * 2] * wt;
                    r.y = acc[mt][nt][h * 2 + 1] * wt;
                    *(float2*)(d_yscr + (size_t)(base + gm) * HDIM + col) = r;
                }
            }
        }
    }
#undef LD2
#undef ST2
}

// ---------------- kernel 6: combine ----------------
__global__ void k_combine(float* __restrict__ out) {
    const int t = blockIdx.x;
    const int s0 = d_slot[2 * t];
    const int s1 = d_slot[2 * t + 1];
    const float* y0 = d_yscr + (size_t)s0 * HDIM;
    const float* y1 = d_yscr + (size_t)s1 * HDIM;
    float* o = out + (size_t)t * HDIM;
    for (int h = threadIdx.x; h < HDIM; h += 256) o[h] = y0[h] + y1[h];
}

// ---------------- launch ----------------
extern "C" void kernel_launch(void* const* d_in, const int* in_sizes, int n_in,
                              void* d_out, int out_size) {
    const float* x    = (const float*)d_in[0];
    const float* Wg   = (const float*)d_in[1];
    const float* Win  = (const float*)d_in[2];
    const float* Wv   = (const float*)d_in[3];
    const float* Wout = (const float*)d_in[4];
    float* out = (float*)d_out;

    float* logits = nullptr;
    if (out_size >= (int)((size_t)T_TOKENS * HDIM + (size_t)T_TOKENS * NEXP))
        logits = out + (size_t)T_TOKENS * HDIM;

    cudaFuncSetAttribute(k_gemm1, cudaFuncAttributeMaxDynamicSharedMemorySize, SM1_BYTES);
    cudaFuncSetAttribute(k_gemm2, cudaFuncAttributeMaxDynamicSharedMemorySize, SM2_BYTES);

    k_zero<<<1, 32>>>();
    k_router<<<T_TOKENS, 256>>>(x, Wg, logits);
    k_scan<<<1, 1>>>();
    k_scatter<<<NPAIR / 256, 256>>>();

    dim3 g1(IDIM / 64, (T_TOKENS + 127) / 128, NEXP);
    k_gemm1<<<g1, 256, SM1_BYTES>>>(x, Win, Wv);

    dim3 g2(HDIM / 128, (T_TOKENS + 127) / 128, NEXP);
    k_gemm2<<<g2, 256, SM2_BYTES>>>(Wout);

    k_combine<<<T_TOKENS, 256>>>(out);
}

// round 7
// speedup vs baseline: 1.3250x; 1.3250x over previous
#include <cuda_runtime.h>
#include <cuda_fp16.h>
#include <cstdint>
#include <math.h>

// Problem constants (FlaxGrok1SparseMoeBlock: B=2,S=1024 -> T=2048, H=1024, I=4096, E=8, K=2)
#define T_TOKENS 2048
#define HDIM 1024
#define IDIM 4096
#define NEXP 8
#define NPAIR (T_TOKENS * 2)

// ---------------- device scratch (static; no runtime allocation) ----------------
__device__ int    d_counts[NEXP];
__device__ int    d_offsets[NEXP];
__device__ int    d_cursor[NEXP];
__device__ int    d_tok[NPAIR];
__device__ float  d_wt[NPAIR];
__device__ int    d_slot[NPAIR];
__device__ int    d_te[NPAIR];
__device__ float  d_tw[NPAIR];
__device__ __half d_act_h[(size_t)NPAIR * IDIM];  // 32 MB (half)
__device__ float  d_yscr[(size_t)NPAIR * HDIM];   // 16 MB

// ---------------- helpers ----------------
__device__ __forceinline__ uint32_t packh2(float lo, float hi) {
    __half2 h = __floats2half2_rn(lo, hi);
    return *(uint32_t*)&h;
}
__device__ __forceinline__ void mma_f16(float c[4], const uint32_t a[4], const uint32_t b[2]) {
    asm volatile(
        "mma.sync.aligned.m16n8k16.row.col.f32.f16.f16.f32 "
        "{%0,%1,%2,%3}, {%4,%5,%6,%7}, {%8,%9}, {%0,%1,%2,%3};"
        : "+f"(c[0]), "+f"(c[1]), "+f"(c[2]), "+f"(c[3])
        : "r"(a[0]), "r"(a[1]), "r"(a[2]), "r"(a[3]), "r"(b[0]), "r"(b[1]));
}
__device__ __forceinline__ float gelu_tanh(float g) {
    float c = g + 0.044715f * g * g * g;
    return 0.5f * g * (1.f + tanhf(0.7978845608028654f * c));
}

// ---------------- kernel 0..3: routing ----------------
__global__ void k_zero() { if (threadIdx.x < NEXP) d_counts[threadIdx.x] = 0; }

__global__ void k_router(const float* __restrict__ x, const float* __restrict__ Wg,
                         float* __restrict__ logits_out) {
    const int t = blockIdx.x;
    const int tid = threadIdx.x;
    const float* xr = x + (size_t)t * HDIM;
    float acc[NEXP];
#pragma unroll
    for (int e = 0; e < NEXP; e++) acc[e] = 0.f;
    for (int h = tid; h < HDIM; h += 256) {
        float xv = xr[h];
#pragma unroll
        for (int e = 0; e < NEXP; e++) acc[e] += xv * Wg[h * NEXP + e];
    }
    __shared__ float red[256];
    __shared__ float lg[NEXP];
#pragma unroll
    for (int e = 0; e < NEXP; e++) {
        red[tid] = acc[e];
        __syncthreads();
        for (int s = 128; s > 0; s >>= 1) { if (tid < s) red[tid] += red[tid + s]; __syncthreads(); }
        if (tid == 0) lg[e] = red[0];
        __syncthreads();
    }
    if (tid == 0) {
        int e0 = 0; float l0 = lg[0];
#pragma unroll
        for (int e = 1; e < NEXP; e++) if (lg[e] > l0) { l0 = lg[e]; e0 = e; }
        int e1 = -1; float l1 = -3.4e38f;
#pragma unroll
        for (int e = 0; e < NEXP; e++) if (e != e0 && lg[e] > l1) { l1 = lg[e]; e1 = e; }
        float tt = expf(l1 - l0);
        float w0 = 1.f / (1.f + tt), w1 = tt / (1.f + tt);
        d_te[2 * t] = e0;     d_tw[2 * t] = w0;
        d_te[2 * t + 1] = e1; d_tw[2 * t + 1] = w1;
        atomicAdd(&d_counts[e0], 1);
        atomicAdd(&d_counts[e1], 1);
        if (logits_out) {
#pragma unroll
            for (int e = 0; e < NEXP; e++) logits_out[(size_t)t * NEXP + e] = lg[e];
        }
    }
}

__global__ void k_scan() {
    int off = 0;
    for (int e = 0; e < NEXP; e++) { d_offsets[e] = off; d_cursor[e] = off; off += d_counts[e]; }
}

__global__ void k_scatter() {
    int i = blockIdx.x * blockDim.x + threadIdx.x;
    if (i >= NPAIR) return;
    int e = d_te[i];
    int pos = atomicAdd(&d_cursor[e], 1);
    d_tok[pos] = i >> 1;
    d_wt[pos]  = d_tw[i];
    d_slot[i]  = pos;
}

// =====================================================================
// GEMM1 (fp16 mma.sync m16n8k16): g=x@Win[e], v=x@Wv[e], act=gelu(g)*v
//   BM=128, BN=64 (per matrix, x2), BK=32; 256 threads; warp tile 32x32
//   3-stage smem pipeline; 2 CTAs/SM for latency hiding
//   smem stage (u32): A[128][20]=2560, Bg[16][72]=1152, Bv=1152 -> 4864
// =====================================================================
#define NCH1 32
#define G1_STG 4864
#define G1_BG  2560
#define G1_BV  3712
#define SM1_BYTES (3 * G1_STG * 4)

__global__ __launch_bounds__(256, 2)
void k_gemm1(const float* __restrict__ x, const float* __restrict__ Win,
             const float* __restrict__ Wv) {
    extern __shared__ uint32_t sm[];
    const int e = blockIdx.z;
    const int cnt = d_counts[e];
    const int m0 = blockIdx.y * 128;
    if (m0 >= cnt) return;
    const int n0 = blockIdx.x * 64;
    const int base = d_offsets[e];
    const int tid = threadIdx.x, lane = tid & 31, wid = tid >> 5;
    const int gid = lane >> 2, t4 = lane & 3;
    const int wm = (wid & 3) * 32, wn = (wid >> 2) * 32;

    // fill mappings
    const int arow = tid >> 1, khalf = tid & 1;
    int gm_a = m0 + arow;
    const float* xrow = x + (size_t)d_tok[base + (gm_a < cnt ? gm_a : cnt - 1)] * HDIM + khalf * 16;
    const int kp = tid >> 4;               // 0..15
    const int nb4 = (tid & 15) * 4;        // 0..60
    const float* wg0 = Win + ((size_t)e * HDIM + 2 * kp) * IDIM + n0 + nb4;
    const float* wv0 = Wv  + ((size_t)e * HDIM + 2 * kp) * IDIM + n0 + nb4;

    float4 pA[4], pG0, pG1, pV0, pV1;

#define G1_LD(c) do { \
        const float* xr_ = xrow + (c) * 32; \
        pA[0] = *(const float4*)(xr_);      pA[1] = *(const float4*)(xr_ + 4); \
        pA[2] = *(const float4*)(xr_ + 8);  pA[3] = *(const float4*)(xr_ + 12); \
        const float* g_ = wg0 + (size_t)(c) * 32 * IDIM; \
        pG0 = *(const float4*)(g_); pG1 = *(const float4*)(g_ + IDIM); \
        const float* v_ = wv0 + (size_t)(c) * 32 * IDIM; \
        pV0 = *(const float4*)(v_); pV1 = *(const float4*)(v_ + IDIM); \
    } while (0)

#define G1_ST(s) do { \
        uint32_t* A_ = sm + (s) * G1_STG; \
        uint4 ua0, ua1; \
        ua0.x = packh2(pA[0].x, pA[0].y); ua0.y = packh2(pA[0].z, pA[0].w); \
        ua0.z = packh2(pA[1].x, pA[1].y); ua0.w = packh2(pA[1].z, pA[1].w); \
        ua1.x = packh2(pA[2].x, pA[2].y); ua1.y = packh2(pA[2].z, pA[2].w); \
        ua1.z = packh2(pA[3].x, pA[3].y); ua1.w = packh2(pA[3].z, pA[3].w); \
        *(uint4*)(A_ + arow * 20 + khalf * 8)     = ua0; \
        *(uint4*)(A_ + arow * 20 + khalf * 8 + 4) = ua1; \
        uint32_t* Bg_ = sm + (s) * G1_STG + G1_BG; \
        uint4 tg; tg.x = packh2(pG0.x, pG1.x); tg.y = packh2(pG0.y, pG1.y); \
                  tg.z = packh2(pG0.z, pG1.z); tg.w = packh2(pG0.w, pG1.w); \
        *(uint4*)(Bg_ + kp * 72 + nb4) = tg; \
        uint32_t* Bv_ = sm + (s) * G1_STG + G1_BV; \
        uint4 tv; tv.x = packh2(pV0.x, pV1.x); tv.y = packh2(pV0.y, pV1.y); \
                  tv.z = packh2(pV0.z, pV1.z); tv.w = packh2(pV0.w, pV1.w); \
        *(uint4*)(Bv_ + kp * 72 + nb4) = tv; \
    } while (0)

    float accg[2][4][4], accv[2][4][4];
#pragma unroll
    for (int i = 0; i < 2; i++)
#pragma unroll
        for (int j = 0; j < 4; j++)
#pragma unroll
            for (int q = 0; q < 4; q++) { accg[i][j][q] = 0.f; accv[i][j][q] = 0.f; }

    G1_LD(0); G1_ST(0); G1_LD(1);
    __syncthreads();

    for (int c = 0; c < NCH1; c++) {
        if (c + 1 < NCH1) G1_ST((c + 1) % 3);
        if (c + 2 < NCH1) G1_LD(c + 2);
        __syncthreads();
        const uint32_t* A_ = sm + (c % 3) * G1_STG;
        const uint32_t* Bg_ = A_ + G1_BG;
        const uint32_t* Bv_ = A_ + G1_BV;
#pragma unroll
        for (int s = 0; s < 2; s++) {
            uint32_t af[2][4];
#pragma unroll
            for (int mt = 0; mt < 2; mt++) {
                int r = wm + mt * 16 + gid;
                af[mt][0] = A_[r * 20 + s * 8 + t4];
                af[mt][1] = A_[(r + 8) * 20 + s * 8 + t4];
                af[mt][2] = A_[r * 20 + s * 8 + t4 + 4];
                af[mt][3] = A_[(r + 8) * 20 + s * 8 + t4 + 4];
            }
#pragma unroll
            for (int nt = 0; nt < 4; nt++) {
                int cidx = wn + nt * 8 + gid;
                uint32_t bg[2] = { Bg_[(s * 8 + t4) * 72 + cidx], Bg_[(s * 8 + t4 + 4) * 72 + cidx] };
                uint32_t bv[2] = { Bv_[(s * 8 + t4) * 72 + cidx], Bv_[(s * 8 + t4 + 4) * 72 + cidx] };
#pragma unroll
                for (int mt = 0; mt < 2; mt++) {
                    mma_f16(accg[mt][nt], af[mt], bg);
                    mma_f16(accv[mt][nt], af[mt], bv);
                }
            }
        }
    }

    // epilogue: act = gelu(g)*v -> half
#pragma unroll
    for (int mt = 0; mt < 2; mt++) {
#pragma unroll
        for (int nt = 0; nt < 4; nt++) {
            int col = n0 + wn + nt * 8 + t4 * 2;
#pragma unroll
            for (int h = 0; h < 2; h++) {
                int gm = m0 + wm + mt * 16 + gid + h * 8;
                if (gm < cnt) {
                    float a0 = gelu_tanh(accg[mt][nt][h * 2])     * accv[mt][nt][h * 2];
                    float a1 = gelu_tanh(accg[mt][nt][h * 2 + 1]) * accv[mt][nt][h * 2 + 1];
                    *(uint32_t*)(d_act_h + (size_t)(base + gm) * IDIM + col) = packh2(a0, a1);
                }
            }
        }
    }
#undef G1_LD
#undef G1_ST
}

// =====================================================================
// GEMM2 (fp16 mma.sync): y = act@Wout[e] * wt
//   BM=128, BN=128, BK=32; 256 threads; warp tile 32x64; 2 CTAs/SM
//   smem stage (u32): A[128][20]=2560, B[16][136]=2176 -> 4736
// =====================================================================
#define NCH2 128
#define G2_STG 4736
#define G2_B   2560
#define SM2_BYTES (3 * G2_STG * 4)

__global__ __launch_bounds__(256, 2)
void k_gemm2(const float* __restrict__ Wout) {
    extern __shared__ uint32_t sm[];
    const int e = blockIdx.z;
    const int cnt = d_counts[e];
    const int m0 = blockIdx.y * 128;
    if (m0 >= cnt) return;
    const int n0 = blockIdx.x * 128;
    const int base = d_offsets[e];
    const int tid = threadIdx.x, lane = tid & 31, wid = tid >> 5;
    const int gid = lane >> 2, t4 = lane & 3;
    const int wm = (wid & 3) * 32, wn = (wid >> 2) * 64;

    const int arow = tid >> 1, khalf = tid & 1;
    int gm_a = m0 + arow;
    int slot_a = base + gm_a;
    if (slot_a > NPAIR - 1) slot_a = NPAIR - 1;
    const __half* actrow = d_act_h + (size_t)slot_a * IDIM + khalf * 16;

    const int kp = tid >> 4;               // 0..15
    const int nb8 = (tid & 15) * 8;        // 0..120
    const float* w0 = Wout + ((size_t)e * IDIM + 2 * kp) * HDIM + n0 + nb8;

    uint4 pA0, pA1;
    float4 pB00, pB01, pB10, pB11;

#define G2_LD(c) do { \
        const __half* ar_ = actrow + (c) * 32; \
        pA0 = *(const uint4*)(ar_); pA1 = *(const uint4*)(ar_ + 8); \
        const float* wr_ = w0 + (size_t)(c) * 32 * HDIM; \
        pB00 = *(const float4*)(wr_);        pB01 = *(const float4*)(wr_ + 4); \
        pB10 = *(const float4*)(wr_ + HDIM); pB11 = *(const float4*)(wr_ + HDIM + 4); \
    } while (0)

#define G2_ST(s) do { \
        uint32_t* A_ = sm + (s) * G2_STG; \
        *(uint4*)(A_ + arow * 20 + khalf * 8)     = pA0; \
        *(uint4*)(A_ + arow * 20 + khalf * 8 + 4) = pA1; \
        uint32_t* B_ = sm + (s) * G2_STG + G2_B; \
        uint4 t0, t1; \
        t0.x = packh2(pB00.x, pB10.x); t0.y = packh2(pB00.y, pB10.y); \
        t0.z = packh2(pB00.z, pB10.z); t0.w = packh2(pB00.w, pB10.w); \
        t1.x = packh2(pB01.x, pB11.x); t1.y = packh2(pB01.y, pB11.y); \
        t1.z = packh2(pB01.z, pB11.z); t1.w = packh2(pB01.w, pB11.w); \
        *(uint4*)(B_ + kp * 136 + nb8)     = t0; \
        *(uint4*)(B_ + kp * 136 + nb8 + 4) = t1; \
    } while (0)

    float acc[2][8][4];
#pragma unroll
    for (int i = 0; i < 2; i++)
#pragma unroll
        for (int j = 0; j < 8; j++)
#pragma unroll
            for (int q = 0; q < 4; q++) acc[i][j][q] = 0.f;

    G2_LD(0); G2_ST(0); G2_LD(1);
    __syncthreads();

    for (int c = 0; c < NCH2; c++) {
        if (c + 1 < NCH2) G2_ST((c + 1) % 3);
        if (c + 2 < NCH2) G2_LD(c + 2);
        __syncthreads();
        const uint32_t* A_ = sm + (c % 3) * G2_STG;
        const uint32_t* B_ = A_ + G2_B;
#pragma unroll
        for (int s = 0; s < 2; s++) {
            uint32_t af[2][4];
#pragma unroll
            for (int mt = 0; mt < 2; mt++) {
                int r = wm + mt * 16 + gid;
                af[mt][0] = A_[r * 20 + s * 8 + t4];
                af[mt][1] = A_[(r + 8) * 20 + s * 8 + t4];
                af[mt][2] = A_[r * 20 + s * 8 + t4 + 4];
                af[mt][3] = A_[(r + 8) * 20 + s * 8 + t4 + 4];
            }
#pragma unroll
            for (int nt = 0; nt < 8; nt++) {
                int cidx = wn + nt * 8 + gid;
                uint32_t bf[2] = { B_[(s * 8 + t4) * 136 + cidx], B_[(s * 8 + t4 + 4) * 136 + cidx] };
#pragma unroll
                for (int mt = 0; mt < 2; mt++) mma_f16(acc[mt][nt], af[mt], bf);
            }
        }
    }

#pragma unroll
    for (int mt = 0; mt < 2; mt++) {
#pragma unroll
        for (int nt = 0; nt < 8; nt++) {
            int col = n0 + wn + nt * 8 + t4 * 2;
#pragma unroll
            for (int h = 0; h < 2; h++) {
                int gm = m0 + wm + mt * 16 + gid + h * 8;
                if (gm < cnt) {
                    float wt = d_wt[base + gm];
                    float2 r;
                    r.x = acc[mt][nt][h * 2] * wt;
                    r.y = acc[mt][nt][h * 2 + 1] * wt;
                    *(float2*)(d_yscr + (size_t)(base + gm) * HDIM + col) = r;
                }
            }
        }
    }
#undef G2_LD
#undef G2_ST
}

// ---------------- kernel 6: combine ----------------
__global__ void k_combine(float* __restrict__ out) {
    const int t = blockIdx.x;
    const int s0 = d_slot[2 * t];
    const int s1 = d_slot[2 * t + 1];
    const float* y0 = d_yscr + (size_t)s0 * HDIM;
    const float* y1 = d_yscr + (size_t)s1 * HDIM;
    float* o = out + (size_t)t * HDIM;
    for (int h = threadIdx.x; h < HDIM; h += 256) o[h] = y0[h] + y1[h];
}

// ---------------- launch ----------------
extern "C" void kernel_launch(void* const* d_in, const int* in_sizes, int n_in,
                              void* d_out, int out_size) {
    const float* x    = (const float*)d_in[0];
    const float* Wg   = (const float*)d_in[1];
    const float* Win  = (const float*)d_in[2];
    const float* Wv   = (const float*)d_in[3];
    const float* Wout = (const float*)d_in[4];
    float* out = (float*)d_out;

    float* logits = nullptr;
    if (out_size >= (int)((size_t)T_TOKENS * HDIM + (size_t)T_TOKENS * NEXP))
        logits = out + (size_t)T_TOKENS * HDIM;

    cudaFuncSetAttribute(k_gemm1, cudaFuncAttributeMaxDynamicSharedMemorySize, SM1_BYTES);
    cudaFuncSetAttribute(k_gemm2, cudaFuncAttributeMaxDynamicSharedMemorySize, SM2_BYTES);

    k_zero<<<1, 32>>>();
    k_router<<<T_TOKENS, 256>>>(x, Wg, logits);
    k_scan<<<1, 1>>>();
    k_scatter<<<NPAIR / 256, 256>>>();

    dim3 g1(IDIM / 64, (T_TOKENS + 127) / 128, NEXP);
    k_gemm1<<<g1, 256, SM1_BYTES>>>(x, Win, Wv);

    dim3 g2(HDIM / 128, (T_TOKENS + 127) / 128, NEXP);
    k_gemm2<<<g2, 256, SM2_BYTES>>>(Wout);

    k_combine<<<T_TOKENS, 256>>>(out);
}